// round 6
// baseline (speedup 1.0000x reference)
#include <cuda_runtime.h>
#include <math.h>

typedef unsigned long long ull;

#define BATCH 4
#define DIM   64
#define HID   170
#define C2    340
#define HW    256
#define NPIX  65536      // 256*256
#define PPR   5          // channel-pairs per round in K1 (10 channels)
#define ROUNDS 34        // 170 pairs / 5

// 356 MB intermediate yr = IDCT(quant * DCT(W_in @ x))
__device__ float g_yr[89128960];  // 4*340*256*256

// ---------- packed fp32x2 helpers (sm_103a) ----------
__device__ __forceinline__ ull pk2(float v) {
    ull r; asm("mov.b64 %0, {%1, %1};" : "=l"(r) : "f"(v)); return r;
}
__device__ __forceinline__ ull pk(float a, float b) {
    ull r; asm("mov.b64 %0, {%1, %2};" : "=l"(r) : "f"(a), "f"(b)); return r;
}
__device__ __forceinline__ ull f2fma(ull a, ull b, ull c) {
    ull d; asm("fma.rn.f32x2 %0, %1, %2, %3;" : "=l"(d) : "l"(a), "l"(b), "l"(c)); return d;
}
__device__ __forceinline__ ull f2mul(ull a, ull b) {
    ull d; asm("mul.rn.f32x2 %0, %1, %2;" : "=l"(d) : "l"(a), "l"(b)); return d;
}
__device__ __forceinline__ void unpk(ull a, float& lo, float& hi) {
    asm("mov.b64 {%0, %1}, %2;" : "=f"(lo), "=f"(hi) : "l"(a));
}

// ======================================================================
// K1: proj_in (1x1 conv 64->340) + per-8x8-patch DCT * quant * IDCT -> g_yr
// Block: 16x16 pixel tile (4 aligned 8x8 patches), 256 threads = 1 px each.
// Channels processed 10 at a time; channel pair (2p, 2p+1) packed in f32x2.
// ======================================================================
__global__ void dctffn_k1(const float* __restrict__ x,
                          const float* __restrict__ Win,
                          const float* __restrict__ quant) {
    extern __shared__ ull sh[];
    ull*   w2 = sh;                         // 170*64 packed W_in pairs
    ull*   SA = sh + 170*64;                // PPR * 16*17
    ull*   SB = SA + PPR*272;
    float* Ms = (float*)(SB + PPR*272);     // M[i][j] (DCT basis)
    float* Mt = Ms + 64;                    // M^T

    const int tid = threadIdx.x;
    const int col = tid & 15, row = tid >> 4;
    const int gx = blockIdx.x*16 + col, gy = blockIdx.y*16 + row;
    const int bz = blockIdx.z;

    // stage packed W_in pairs: w2[p*64+k] = {Win[2p][k], Win[2p+1][k]}
    for (int idx = tid; idx < 170*64; idx += 256) {
        int p = idx >> 6, k = idx & 63;
        w2[idx] = pk(Win[(2*p)*64 + k], Win[(2*p+1)*64 + k]);
    }
    // orthonormal DCT-II basis (P=8): M[0][j]=sqrt(1/8); M[i][j]=0.5*cos(pi*i*(2j+1)/16)
    if (tid < 64) {
        int i = tid >> 3, j = tid & 7;
        float v = (i == 0) ? 0.35355339059327376f
                           : 0.5f * cospif((float)(i*(2*j+1)) * 0.0625f);
        Ms[i*8 + j] = v;
        Mt[j*8 + i] = v;
    }

    // this thread's 64 input-channel values -> registers
    float xr[64];
    const float* xp = x + (size_t)bz*DIM*NPIX + gy*HW + gx;
    #pragma unroll
    for (int k = 0; k < 64; k++) xr[k] = xp[k*NPIX];

    const int prow = row & 7, pcol = col & 7;
    const int rb17 = (row & ~7) * 17;   // patch row base * pitch
    const int cb   = col & ~7;          // patch col base
    const int ti   = row*17 + col;
    float* yo = g_yr + (size_t)bz*C2*NPIX + gy*HW + gx;

    __syncthreads();

    for (int rd = 0; rd < ROUNDS; rd++) {
        const int p0 = rd*PPR;

        // ---- proj_in: y = W_in @ x  (64 f32x2 FMA per pair) ----
        ull acc[PPR];
        #pragma unroll
        for (int p = 0; p < PPR; p++) acc[p] = 0ull;
        #pragma unroll
        for (int k = 0; k < 64; k += 2) {
            ull x0 = pk2(xr[k]), x1 = pk2(xr[k+1]);
            #pragma unroll
            for (int p = 0; p < PPR; p++) {
                ulonglong2 w = *(const ulonglong2*)&w2[(p0+p)*64 + k];
                acc[p] = f2fma(w.x, x0, acc[p]);
                acc[p] = f2fma(w.y, x1, acc[p]);
            }
        }
        #pragma unroll
        for (int p = 0; p < PPR; p++) SA[p*272 + ti] = acc[p];
        __syncthreads();

        // ---- pass1: T1[pr,b] = sum_q X[pr,q] * M[b,q]   (b = pcol) ----
        {
            ull a2[PPR];
            #pragma unroll
            for (int p = 0; p < PPR; p++) a2[p] = 0ull;
            const float* m = Ms + pcol*8;
            const ull* src = SA + row*17 + cb;
            #pragma unroll
            for (int q = 0; q < 8; q++) {
                ull m2 = pk2(m[q]);
                #pragma unroll
                for (int p = 0; p < PPR; p++) a2[p] = f2fma(m2, src[p*272 + q], a2[p]);
            }
            #pragma unroll
            for (int p = 0; p < PPR; p++) SB[p*272 + ti] = a2[p];
        }
        __syncthreads();

        // ---- pass2: D[a,b] = sum_p M[a,p] * T1[p,b]  (a = prow); D *= quant ----
        {
            ull a2[PPR];
            #pragma unroll
            for (int p = 0; p < PPR; p++) a2[p] = 0ull;
            const float* m = Ms + prow*8;
            const ull* src = SB + rb17 + col;
            #pragma unroll
            for (int q = 0; q < 8; q++) {
                ull m2 = pk2(m[q]);
                #pragma unroll
                for (int p = 0; p < PPR; p++) a2[p] = f2fma(m2, src[p*272 + q*17], a2[p]);
            }
            const int fidx = prow*8 + pcol;
            #pragma unroll
            for (int p = 0; p < PPR; p++) {
                int c0 = (p0 + p) * 2;
                ull q2 = pk(__ldg(quant + c0*64 + fidx), __ldg(quant + (c0+1)*64 + fidx));
                SA[p*272 + ti] = f2mul(a2[p], q2);
            }
        }
        __syncthreads();

        // ---- pass3: T2[a,j] = sum_b D[a,b] * M[b,j]  (j = pcol) ----
        {
            ull a2[PPR];
            #pragma unroll
            for (int p = 0; p < PPR; p++) a2[p] = 0ull;
            const float* m = Mt + pcol*8;    // Mt[j][b] = M[b][j]
            const ull* src = SA + row*17 + cb;
            #pragma unroll
            for (int q = 0; q < 8; q++) {
                ull m2 = pk2(m[q]);
                #pragma unroll
                for (int p = 0; p < PPR; p++) a2[p] = f2fma(m2, src[p*272 + q], a2[p]);
            }
            #pragma unroll
            for (int p = 0; p < PPR; p++) SB[p*272 + ti] = a2[p];
        }
        __syncthreads();

        // ---- pass4: X'[i,j] = sum_a M[a,i] * T2[a,j]  (i = prow); store ----
        {
            ull a2[PPR];
            #pragma unroll
            for (int p = 0; p < PPR; p++) a2[p] = 0ull;
            const float* m = Mt + prow*8;    // Mt[i][a] = M[a][i]
            const ull* src = SB + rb17 + col;
            #pragma unroll
            for (int q = 0; q < 8; q++) {
                ull m2 = pk2(m[q]);
                #pragma unroll
                for (int p = 0; p < PPR; p++) a2[p] = f2fma(m2, src[p*272 + q*17], a2[p]);
            }
            #pragma unroll
            for (int p = 0; p < PPR; p++) {
                int c0 = (p0 + p) * 2;
                float lo, hi; unpk(a2[p], lo, hi);
                yo[c0*NPIX]       = lo;
                yo[(c0+1)*NPIX]   = hi;
            }
        }
        // no sync needed: next conv touches only SA (covered by post-pass3 sync);
        // next pass1 writes SB only after the post-conv sync.
    }
}

// ======================================================================
// K2: depthwise 3x3 + exact-GELU gating + proj_out (170->64), fused.
// Block: 16x16 tile; each thread holds 64 out-channel accs as 32 f32x2.
// Per-channel halo tiles double-buffered through registers.
// ======================================================================
__global__ void dctffn_k2(const float* __restrict__ Wdw,
                          const float* __restrict__ Wout,
                          float* __restrict__ out) {
    extern __shared__ ull sh[];
    ull*   wo2 = sh;                         // 170*32 packed W_out pairs
    float* wd  = (float*)(wo2 + 170*32);     // 3060 dw weights
    float* s1  = wd + 3060;                  // 18x18 halo tile, pitch 19
    float* s2  = s1 + 344;

    const int tid = threadIdx.x;
    const int col = tid & 15, row = tid >> 4;
    const int bz = blockIdx.z;
    const int gx = blockIdx.x*16 + col, gy = blockIdx.y*16 + row;

    for (int idx = tid; idx < 3060; idx += 256) wd[idx] = Wdw[idx];
    for (int idx = tid; idx < 170*32; idx += 256) {
        int c = idx >> 5, o2 = idx & 31;
        wo2[idx] = pk(Wout[(2*o2)*HID + c], Wout[(2*o2+1)*HID + c]);
    }

    ull acc[32];
    #pragma unroll
    for (int o = 0; o < 32; o++) acc[o] = 0ull;

    const float* yrb = g_yr + (size_t)bz*C2*NPIX;
    const int y0 = blockIdx.y*16 - 1, x0 = blockIdx.x*16 - 1;

    // halo-load slot geometry (invariant over channels)
    const int i0 = tid;                     // always < 324
    const int ly0 = i0 / 18, lx0 = i0 % 18;
    const int yy0 = y0 + ly0, xx0 = x0 + lx0;
    const bool ok0 = ((unsigned)yy0 < 256u) && ((unsigned)xx0 < 256u);
    const int off0 = yy0*HW + xx0;
    const int sidx0 = ly0*19 + lx0;

    const int i1 = tid + 256;
    const bool valid1 = i1 < 324;
    const int ly1 = i1 / 18, lx1 = i1 % 18;
    const int yy1 = y0 + ly1, xx1 = x0 + lx1;
    const bool ok1 = valid1 && ((unsigned)yy1 < 256u) && ((unsigned)xx1 < 256u);
    const int off1 = yy1*HW + xx1;
    const int sidx1 = ly1*19 + lx1;

    // prefetch channel 0
    float r1a, r2a, r1b = 0.f, r2b = 0.f;
    {
        const float* p1 = yrb;
        const float* p2 = yrb + (size_t)HID*NPIX;
        r1a = ok0 ? __ldg(p1 + off0) : 0.f;
        r2a = ok0 ? __ldg(p2 + off0) : 0.f;
        if (valid1) {
            r1b = ok1 ? __ldg(p1 + off1) : 0.f;
            r2b = ok1 ? __ldg(p2 + off1) : 0.f;
        }
    }
    __syncthreads();  // wd / wo2 staged

    for (int c = 0; c < 170; c++) {
        s1[sidx0] = r1a; s2[sidx0] = r2a;
        if (valid1) { s1[sidx1] = r1b; s2[sidx1] = r2b; }
        __syncthreads();

        if (c + 1 < 170) {  // prefetch next channel (latency hides under compute)
            const float* p1 = yrb + (size_t)(c+1)*NPIX;
            const float* p2 = p1 + (size_t)HID*NPIX;
            r1a = ok0 ? __ldg(p1 + off0) : 0.f;
            r2a = ok0 ? __ldg(p2 + off0) : 0.f;
            if (valid1) {
                r1b = ok1 ? __ldg(p1 + off1) : 0.f;
                r2b = ok1 ? __ldg(p2 + off1) : 0.f;
            }
        }

        // depthwise 3x3 (cross-correlation, zero pad)
        const float* ka = wd + c*9;
        const float* kb = wd + (c + 170)*9;
        float d1 = 0.f, d2 = 0.f;
        #pragma unroll
        for (int u = 0; u < 3; u++)
            #pragma unroll
            for (int v = 0; v < 3; v++) {
                d1 = fmaf(s1[(row+u)*19 + col+v], ka[u*3+v], d1);
                d2 = fmaf(s2[(row+u)*19 + col+v], kb[u*3+v], d2);
            }

        // exact GELU(d1) * d2
        float g = 0.5f * d1 * (1.0f + erff(d1 * 0.70710678118654752f)) * d2;
        ull g2 = pk2(g);

        // proj_out rank-1 update: acc[o] += W_out[o][c] * g
        const ull* wr = wo2 + c*32;
        #pragma unroll
        for (int o = 0; o < 32; o += 2) {
            ulonglong2 w = *(const ulonglong2*)(wr + o);
            acc[o]   = f2fma(w.x, g2, acc[o]);
            acc[o+1] = f2fma(w.y, g2, acc[o+1]);
        }
        __syncthreads();
    }

    float* ob = out + (size_t)bz*DIM*NPIX + gy*HW + gx;
    #pragma unroll
    for (int o2 = 0; o2 < 32; o2++) {
        float lo, hi; unpk(acc[o2], lo, hi);
        ob[(2*o2)*NPIX]     = lo;
        ob[(2*o2+1)*NPIX]   = hi;
    }
}

// ======================================================================
extern "C" void kernel_launch(void* const* d_in, const int* in_sizes, int n_in,
                              void* d_out, int out_size) {
    const float* x     = (const float*)d_in[0];
    const float* Win   = (const float*)d_in[1];
    const float* Wdw   = (const float*)d_in[2];
    const float* quant = (const float*)d_in[3];
    const float* Wout  = (const float*)d_in[4];
    float* out = (float*)d_out;

    constexpr int SM1 = (170*64 + 2*PPR*272) * 8 + 128 * 4;      // 109312 B
    constexpr int SM2 = 170*32*8 + (3060 + 344 + 344) * 4;       // 58512 B

    cudaFuncSetAttribute(dctffn_k1, cudaFuncAttributeMaxDynamicSharedMemorySize, SM1);
    cudaFuncSetAttribute(dctffn_k2, cudaFuncAttributeMaxDynamicSharedMemorySize, SM2);

    dim3 grid(16, 16, 4), blk(256, 1, 1);
    dctffn_k1<<<grid, blk, SM1>>>(x, Win, quant);
    dctffn_k2<<<grid, blk, SM2>>>(Wdw, Wout, out);
}

// round 10
// speedup vs baseline: 1.1511x; 1.1511x over previous
#include <cuda_runtime.h>
#include <math.h>

typedef unsigned long long ull;

#define DIM   64
#define HID   170
#define C2    340
#define HW    256
#define NPIX  65536      // 256*256
#define PPR   5          // channel-pairs per round in K1'
#define ROUNDS 34        // 170 pairs / 5

// intermediates
__device__ float g_xd[16777216];   // 4* 64*65536 : DCT(x)
__device__ float g_yr[89128960];   // 4*340*65536 : IDCT(quant * (W_in @ DCT(x)))
__device__ float g_g [44564480];   // 4*170*65536 : gelu(dw1) * dw2

// ---------- packed fp32x2 helpers (sm_103a) ----------
__device__ __forceinline__ ull pk2(float v) {
    ull r; asm("mov.b64 %0, {%1, %1};" : "=l"(r) : "f"(v)); return r;
}
__device__ __forceinline__ ull pk(float a, float b) {
    ull r; asm("mov.b64 %0, {%1, %2};" : "=l"(r) : "f"(a), "f"(b)); return r;
}
__device__ __forceinline__ ull f2fma(ull a, ull b, ull c) {
    ull d; asm("fma.rn.f32x2 %0, %1, %2, %3;" : "=l"(d) : "l"(a), "l"(b), "l"(c)); return d;
}
__device__ __forceinline__ ull f2mul(ull a, ull b) {
    ull d; asm("mul.rn.f32x2 %0, %1, %2;" : "=l"(d) : "l"(a), "l"(b)); return d;
}
__device__ __forceinline__ void unpk(ull a, float& lo, float& hi) {
    asm("mov.b64 {%0, %1}, %2;" : "=f"(lo), "=f"(hi) : "l"(a));
}

// ======================================================================
// K0: per-8x8-patch 2-D DCT of the 64 INPUT channels: g_xd = M x M^T.
// Block: 16x16 pixel tile, thread = 1 px; 2 rounds of 16 channel-pairs.
// ======================================================================
__global__ void k0_dct(const float* __restrict__ x) {
    extern __shared__ ull sh[];
    ull*   SA = sh;                  // 16 * 272
    ull*   SB = SA + 16*272;
    float* Ms = (float*)(SB + 16*272);

    const int tid = threadIdx.x;
    const int col = tid & 15, row = tid >> 4;
    const int gx = blockIdx.x*16 + col, gy = blockIdx.y*16 + row;
    const int bz = blockIdx.z;

    if (tid < 64) {
        int i = tid >> 3, j = tid & 7;
        Ms[i*8 + j] = (i == 0) ? 0.35355339059327376f
                               : 0.5f * cospif((float)(i*(2*j+1)) * 0.0625f);
    }

    // 64 input channels as 32 pairs -> registers
    ull xq[32];
    const float* xp = x + (size_t)bz*DIM*NPIX + gy*HW + gx;
    #pragma unroll
    for (int p = 0; p < 32; p++)
        xq[p] = pk(xp[(2*p)*NPIX], xp[(2*p+1)*NPIX]);

    const int prow = row & 7, pcol = col & 7;
    const int rb17 = (row & ~7) * 17;
    const int cb   = col & ~7;
    const int ti   = row*17 + col;
    float* yo = g_xd + (size_t)bz*DIM*NPIX + gy*HW + gx;

    __syncthreads();

    #pragma unroll
    for (int rd = 0; rd < 2; rd++) {
        #pragma unroll
        for (int p = 0; p < 16; p++) SA[p*272 + ti] = xq[rd*16 + p];
        __syncthreads();

        // pass1 (row): T1[pr,b] = sum_q X[pr,q] * M[b,q]   (b = pcol)
        {
            ull a2[16];
            #pragma unroll
            for (int p = 0; p < 16; p++) a2[p] = 0ull;
            const float* m = Ms + pcol*8;
            const ull* src = SA + row*17 + cb;
            #pragma unroll
            for (int q = 0; q < 8; q++) {
                ull m2 = pk2(m[q]);
                #pragma unroll
                for (int p = 0; p < 16; p++) a2[p] = f2fma(m2, src[p*272 + q], a2[p]);
            }
            #pragma unroll
            for (int p = 0; p < 16; p++) SB[p*272 + ti] = a2[p];
        }
        __syncthreads();

        // pass2 (col): D[a,b] = sum_p M[a,p] * T1[p,b]  (a = prow); store
        {
            ull a2[16];
            #pragma unroll
            for (int p = 0; p < 16; p++) a2[p] = 0ull;
            const float* m = Ms + prow*8;
            const ull* src = SB + rb17 + col;
            #pragma unroll
            for (int q = 0; q < 8; q++) {
                ull m2 = pk2(m[q]);
                #pragma unroll
                for (int p = 0; p < 16; p++) a2[p] = f2fma(m2, src[p*272 + q*17], a2[p]);
            }
            #pragma unroll
            for (int p = 0; p < 16; p++) {
                int c0 = (rd*16 + p) * 2;
                float lo, hi; unpk(a2[p], lo, hi);
                yo[c0*NPIX]     = lo;
                yo[(c0+1)*NPIX] = hi;
            }
        }
        // next-round SA store is guarded by the sync at the top of the round
    }
}

// ======================================================================
// K1': DCT-domain 1x1 conv (64->340) * quant, then 2-pass IDCT -> g_yr.
// (DCT commutes with the per-pixel channel mix: D = W_in @ DCT(x).)
// ======================================================================
__global__ void k1_idct(const float* __restrict__ Win,
                        const float* __restrict__ quant) {
    extern __shared__ ull sh[];
    ull*   w2 = sh;                      // 170*64 packed W_in pairs
    ull*   SA = sh + 170*64;             // PPR * 272
    ull*   SB = SA + PPR*272;
    float* Mt = (float*)(SB + PPR*272);  // M^T

    const int tid = threadIdx.x;
    const int col = tid & 15, row = tid >> 4;
    const int gx = blockIdx.x*16 + col, gy = blockIdx.y*16 + row;
    const int bz = blockIdx.z;

    for (int idx = tid; idx < 170*64; idx += 256) {
        int p = idx >> 6, k = idx & 63;
        w2[idx] = pk(Win[(2*p)*64 + k], Win[(2*p+1)*64 + k]);
    }
    if (tid < 64) {
        int i = tid >> 3, j = tid & 7;
        float v = (i == 0) ? 0.35355339059327376f
                           : 0.5f * cospif((float)(i*(2*j+1)) * 0.0625f);
        Mt[j*8 + i] = v;
    }

    // this thread's 64 DCT-domain input values -> registers
    float xr[64];
    const float* xp = g_xd + (size_t)bz*DIM*NPIX + gy*HW + gx;
    #pragma unroll
    for (int k = 0; k < 64; k++) xr[k] = xp[k*NPIX];

    const int prow = row & 7, pcol = col & 7;
    const int rb17 = (row & ~7) * 17;
    const int cb   = col & ~7;
    const int ti   = row*17 + col;
    const int fidx = prow*8 + pcol;       // this thread's frequency index
    float* yo = g_yr + (size_t)bz*C2*NPIX + gy*HW + gx;

    __syncthreads();

    for (int rd = 0; rd < ROUNDS; rd++) {
        const int p0 = rd*PPR;

        // ---- conv: D = W_in @ Xd, then * quant (per-thread frequency) ----
        ull acc[PPR];
        #pragma unroll
        for (int p = 0; p < PPR; p++) acc[p] = 0ull;
        #pragma unroll
        for (int k = 0; k < 64; k += 2) {
            ull x0 = pk2(xr[k]), x1 = pk2(xr[k+1]);
            #pragma unroll
            for (int p = 0; p < PPR; p++) {
                ulonglong2 w = *(const ulonglong2*)&w2[(p0+p)*64 + k];
                acc[p] = f2fma(w.x, x0, acc[p]);
                acc[p] = f2fma(w.y, x1, acc[p]);
            }
        }
        #pragma unroll
        for (int p = 0; p < PPR; p++) {
            int c0 = (p0 + p) * 2;
            ull q2 = pk(__ldg(quant + c0*64 + fidx), __ldg(quant + (c0+1)*64 + fidx));
            SA[p*272 + ti] = f2mul(acc[p], q2);
        }
        __syncthreads();

        // ---- IDCT pass A (row): T[a,j] = sum_b D[a,b] * M[b,j]  (j = pcol) ----
        {
            ull a2[PPR];
            #pragma unroll
            for (int p = 0; p < PPR; p++) a2[p] = 0ull;
            const float* m = Mt + pcol*8;        // Mt[j][b] = M[b][j]
            const ull* src = SA + row*17 + cb;
            #pragma unroll
            for (int q = 0; q < 8; q++) {
                ull m2 = pk2(m[q]);
                #pragma unroll
                for (int p = 0; p < PPR; p++) a2[p] = f2fma(m2, src[p*272 + q], a2[p]);
            }
            #pragma unroll
            for (int p = 0; p < PPR; p++) SB[p*272 + ti] = a2[p];
        }
        __syncthreads();

        // ---- IDCT pass B (col): X'[i,j] = sum_a M[a,i] * T[a,j]  (i = prow) ----
        {
            ull a2[PPR];
            #pragma unroll
            for (int p = 0; p < PPR; p++) a2[p] = 0ull;
            const float* m = Mt + prow*8;        // Mt[i][a] = M[a][i]
            const ull* src = SB + rb17 + col;
            #pragma unroll
            for (int q = 0; q < 8; q++) {
                ull m2 = pk2(m[q]);
                #pragma unroll
                for (int p = 0; p < PPR; p++) a2[p] = f2fma(m2, src[p*272 + q*17], a2[p]);
            }
            #pragma unroll
            for (int p = 0; p < PPR; p++) {
                int c0 = (p0 + p) * 2;
                float lo, hi; unpk(a2[p], lo, hi);
                yo[c0*NPIX]     = lo;
                yo[(c0+1)*NPIX] = hi;
            }
        }
        // hazards on SA (next conv-store) and SB (next pass A write) are both
        // covered by the two syncs above — see derivation in commit message.
    }
}

// ======================================================================
// K2a: depthwise 3x3 + exact-GELU gating -> g_g. Double-buffered halo,
// one barrier per channel, no weight-matrix accumulators -> high occupancy.
// ======================================================================
__global__ void k2a_dwgelu(const float* __restrict__ Wdw) {
    __shared__ float wd[3060];
    __shared__ float s1[2][344];
    __shared__ float s2[2][344];

    const int tid = threadIdx.x;
    const int col = tid & 15, row = tid >> 4;
    const int bz = blockIdx.z;
    const int gx = blockIdx.x*16 + col, gy = blockIdx.y*16 + row;

    for (int idx = tid; idx < 3060; idx += 256) wd[idx] = Wdw[idx];

    const float* yrb = g_yr + (size_t)bz*C2*NPIX;
    const int y0 = blockIdx.y*16 - 1, x0 = blockIdx.x*16 - 1;

    const int i0 = tid;
    const int ly0 = i0 / 18, lx0 = i0 % 18;
    const int yy0 = y0 + ly0, xx0 = x0 + lx0;
    const bool ok0 = ((unsigned)yy0 < 256u) && ((unsigned)xx0 < 256u);
    const int off0 = yy0*HW + xx0;
    const int sidx0 = ly0*19 + lx0;

    const int i1 = tid + 256;
    const bool valid1 = i1 < 324;
    const int ly1 = i1 / 18, lx1 = i1 % 18;
    const int yy1 = y0 + ly1, xx1 = x0 + lx1;
    const bool ok1 = valid1 && ((unsigned)yy1 < 256u) && ((unsigned)xx1 < 256u);
    const int off1 = yy1*HW + xx1;
    const int sidx1 = ly1*19 + lx1;

    // prefetch channel 0
    float r1a, r2a, r1b = 0.f, r2b = 0.f;
    {
        const float* p1 = yrb;
        const float* p2 = yrb + (size_t)HID*NPIX;
        r1a = ok0 ? __ldg(p1 + off0) : 0.f;
        r2a = ok0 ? __ldg(p2 + off0) : 0.f;
        if (valid1) {
            r1b = ok1 ? __ldg(p1 + off1) : 0.f;
            r2b = ok1 ? __ldg(p2 + off1) : 0.f;
        }
    }

    float* go = g_g + (size_t)bz*HID*NPIX + gy*HW + gx;

    for (int c = 0; c < 170; c++) {
        const int sb = c & 1;
        s1[sb][sidx0] = r1a; s2[sb][sidx0] = r2a;
        if (valid1) { s1[sb][sidx1] = r1b; s2[sb][sidx1] = r2b; }
        __syncthreads();

        if (c + 1 < 170) {
            const float* p1 = yrb + (size_t)(c+1)*NPIX;
            const float* p2 = p1 + (size_t)HID*NPIX;
            r1a = ok0 ? __ldg(p1 + off0) : 0.f;
            r2a = ok0 ? __ldg(p2 + off0) : 0.f;
            if (valid1) {
                r1b = ok1 ? __ldg(p1 + off1) : 0.f;
                r2b = ok1 ? __ldg(p2 + off1) : 0.f;
            }
        }

        const float* ka = wd + c*9;
        const float* kb = wd + (c + 170)*9;
        float d1 = 0.f, d2 = 0.f;
        #pragma unroll
        for (int u = 0; u < 3; u++)
            #pragma unroll
            for (int v = 0; v < 3; v++) {
                d1 = fmaf(s1[sb][(row+u)*19 + col+v], ka[u*3+v], d1);
                d2 = fmaf(s2[sb][(row+u)*19 + col+v], kb[u*3+v], d2);
            }

        go[c*NPIX] = 0.5f * d1 * (1.0f + erff(d1 * 0.70710678118654752f)) * d2;
        // no second barrier: double buffering + the one sync above make the
        // (c+1) halo store safe against this channel's conv reads.
    }
}

// ======================================================================
// K2b: proj_out GEMM, out[64 x N] = Wout[64 x 170] @ g[170 x N].
// Block: 64 out-ch x 256 px; thread: 8 out-ch x 8 px (acc = 32 f32x2).
// g staged per 17-k chunk; weights staged once; ~2B smem per f2fma.
// ======================================================================
__global__ void k2b_proj(const float* __restrict__ Wout,
                         float* __restrict__ out) {
    extern __shared__ float shf[];
    float* w_s = shf;              // 64*170
    float* g_s = w_s + 64*170;     // 17*256

    const int tid = threadIdx.x;
    const int pg = tid & 31;       // px group (32 groups)
    const int cg = tid >> 5;       // out-channel group (8 groups of 8)
    const int b = blockIdx.y;
    const int pixbase = blockIdx.x * 256;

    for (int idx = tid; idx < 64*170; idx += 256) w_s[idx] = Wout[idx];

    const float* gsrc = g_g + (size_t)b*HID*NPIX + pixbase;

    ull acc[8][4];
    #pragma unroll
    for (int i = 0; i < 8; i++)
        #pragma unroll
        for (int j = 0; j < 4; j++) acc[i][j] = 0ull;

    for (int k0 = 0; k0 < 170; k0 += 17) {
        __syncthreads();   // also orders w_s staging before first use
        #pragma unroll
        for (int t = 0; t < 17; t++) {
            int idx = t*256 + tid;
            g_s[idx] = gsrc[(size_t)(k0 + t)*NPIX + tid];
        }
        __syncthreads();

        #pragma unroll
        for (int kk = 0; kk < 17; kk++) {
            ull wr[8];
            const float* wcol = w_s + (cg*8)*170 + (k0 + kk);
            #pragma unroll
            for (int i = 0; i < 8; i++) wr[i] = pk2(wcol[i*170]);   // warp-uniform broadcast
            ull g2[4];
            const float* gr = g_s + kk*256 + 2*pg;
            #pragma unroll
            for (int j = 0; j < 4; j++) g2[j] = *(const ull*)(gr + 64*j);
            #pragma unroll
            for (int i = 0; i < 8; i++)
                #pragma unroll
                for (int j = 0; j < 4; j++)
                    acc[i][j] = f2fma(wr[i], g2[j], acc[i][j]);
        }
    }

    float* ob = out + (size_t)b*DIM*NPIX + pixbase + 2*pg;
    #pragma unroll
    for (int i = 0; i < 8; i++) {
        const int ch = cg*8 + i;
        #pragma unroll
        for (int j = 0; j < 4; j++) {
            float lo, hi; unpk(acc[i][j], lo, hi);
            float2 v; v.x = lo; v.y = hi;
            *(float2*)(ob + (size_t)ch*NPIX + 64*j) = v;
        }
    }
}

// ======================================================================
extern "C" void kernel_launch(void* const* d_in, const int* in_sizes, int n_in,
                              void* d_out, int out_size) {
    const float* x     = (const float*)d_in[0];
    const float* Win   = (const float*)d_in[1];
    const float* Wdw   = (const float*)d_in[2];
    const float* quant = (const float*)d_in[3];
    const float* Wout  = (const float*)d_in[4];
    float* out = (float*)d_out;

    constexpr int SM0 = 2*16*272*8 + 64*4;                 // 69888
    constexpr int SM1 = (170*64 + 2*PPR*272) * 8 + 64*4;   // 109056
    constexpr int SM2 = (64*170 + 17*256) * 4;             // 60928

    cudaFuncSetAttribute(k0_dct,  cudaFuncAttributeMaxDynamicSharedMemorySize, SM0);
    cudaFuncSetAttribute(k1_idct, cudaFuncAttributeMaxDynamicSharedMemorySize, SM1);
    cudaFuncSetAttribute(k2b_proj,cudaFuncAttributeMaxDynamicSharedMemorySize, SM2);

    dim3 grid(16, 16, 4), blk(256, 1, 1);
    k0_dct  <<<grid, blk, SM0>>>(x);
    k1_idct <<<grid, blk, SM1>>>(Win, quant);
    k2a_dwgelu<<<grid, blk>>>(Wdw);
    dim3 grid2(256, 4, 1);
    k2b_proj<<<grid2, blk, SM2>>>(Wout, out);
}